// round 3
// baseline (speedup 1.0000x reference)
#include <cuda_runtime.h>
#include <cstdint>
#include <cstddef>
#include <math.h>

#define B_TOT 131072
#define D_IN  128
#define HID   256
#define VTOT  6
#define TSTEPS 6

// libdevice direct (immune to -use_fast_math macro substitution; matches XLA)
extern "C" __device__ float __nv_logf(float);
extern "C" __device__ float __nv_expf(float);

// ---------------- persistent device scratch (no runtime allocations) -------
__device__ __align__(16) float g_h [(size_t)B_TOT * HID];
__device__ __align__(16) float g_z [(size_t)B_TOT * HID];
__device__ __align__(16) float g_rh[(size_t)B_TOT * HID];
__device__ unsigned char g_state[B_TOT];        // bits[2:0]=embed state 0..7, bit3=stopped
__device__ __align__(16) float g_E[3][8][HID];  // [z,r,h][state][j] = emb_s @ W_top + bias
__device__ uint32_t g_keyw[12];                 // split(key(42), 6) -> 6 key pairs

// ---------------- threefry2x32 (exact JAX schedule) -------------------------
__device__ __forceinline__ void threefry2x32(uint32_t k0, uint32_t k1,
                                             uint32_t c0, uint32_t c1,
                                             uint32_t& o0, uint32_t& o1) {
  uint32_t ks2 = k0 ^ k1 ^ 0x1BD11BDAu;
  uint32_t x0 = c0 + k0, x1 = c1 + k1;
#define TF_R(r) { x0 += x1; x1 = (x1 << (r)) | (x1 >> (32 - (r))); x1 ^= x0; }
  TF_R(13) TF_R(15) TF_R(26) TF_R(6)
  x0 += k1;  x1 += ks2 + 1u;
  TF_R(17) TF_R(29) TF_R(16) TF_R(24)
  x0 += ks2; x1 += k0 + 2u;
  TF_R(13) TF_R(15) TF_R(26) TF_R(6)
  x0 += k0;  x1 += k1 + 3u;
  TF_R(17) TF_R(29) TF_R(16) TF_R(24)
  x0 += k1;  x1 += ks2 + 4u;
  TF_R(13) TF_R(15) TF_R(26) TF_R(6)
  x0 += ks2; x1 += k0 + 5u;
#undef TF_R
  o0 = x0; o1 = x1;
}

// ---------------- small helpers ---------------------------------------------
__device__ __forceinline__ void fma2(unsigned long long& d,
                                     unsigned long long a,
                                     unsigned long long b) {
  asm("fma.rn.f32x2 %0, %1, %2, %0;" : "+l"(d) : "l"(a), "l"(b));
}
__device__ __forceinline__ unsigned long long pack2(float a) {
  unsigned long long r;
  asm("mov.b64 %0, {%1, %1};" : "=l"(r) : "f"(a));
  return r;
}
__device__ __forceinline__ float2 unpack2(unsigned long long v) {
  float2 r;
  asm("mov.b64 {%0, %1}, %2;" : "=f"(r.x), "=f"(r.y) : "l"(v));
  return r;
}
__device__ __forceinline__ void cp16(void* dst, const void* src) {
  unsigned d = (unsigned)__cvta_generic_to_shared(dst);
  asm volatile("cp.async.cg.shared.global [%0], [%1], 16;" :: "r"(d), "l"(src));
}

// ---- XLA EmitFastTanh replication (no FMA contraction, IEEE div) -----------
__device__ __forceinline__ float xla_tanh(float x) {
  float ax = fabsf(x);
  if (ax < 0.0004f) return x;
  float xc = fminf(fmaxf(x, -9.0f), 9.0f);
  float x2 = __fmul_rn(xc, xc);
  float num = -2.76076847742355e-16f;
  num = __fadd_rn(__fmul_rn(x2, num), 2.00018790482477e-13f);
  num = __fadd_rn(__fmul_rn(x2, num), -8.60467152213735e-11f);
  num = __fadd_rn(__fmul_rn(x2, num), 5.12229709037114e-08f);
  num = __fadd_rn(__fmul_rn(x2, num), 1.48572235717979e-05f);
  num = __fadd_rn(__fmul_rn(x2, num), 6.37261928875436e-04f);
  num = __fadd_rn(__fmul_rn(x2, num), 4.89352455891786e-03f);
  num = __fmul_rn(xc, num);
  float den = 1.19825839466702e-06f;
  den = __fadd_rn(__fmul_rn(x2, den), 1.18534705686654e-04f);
  den = __fadd_rn(__fmul_rn(x2, den), 2.26843463243900e-03f);
  den = __fadd_rn(__fmul_rn(x2, den), 4.89352518554385e-03f);
  return __fdiv_rn(num, den);
}
// XLA logistic lowering: 0.5 + 0.5 * tanh(0.5 * x)
__device__ __forceinline__ float sigmoid_(float x) {
  return __fadd_rn(0.5f, __fmul_rn(0.5f, xla_tanh(__fmul_rn(0.5f, x))));
}

// ---------------- init: out accumulators, state, step keys ------------------
// Partitionable split: key_t = (o0, o1) of threefry(key, (0, t))
__global__ void init_kernel(float* __restrict__ out) {
  int i = blockIdx.x * blockDim.x + threadIdx.x;
  if (i < B_TOT) {
    out[(size_t)B_TOT * 36 + i] = 0.f;   // total_log_prob
    out[(size_t)B_TOT * 37 + i] = 0.f;   // lengths
    g_state[i] = 7;                      // start_embed, not stopped
  }
  if (i < 6) {
    uint32_t a, b;
    threefry2x32(0u, 42u, 0u, (uint32_t)i, a, b);
    g_keyw[2 * i]     = a;
    g_keyw[2 * i + 1] = b;
  }
}

// ---------------- precompute E tables: 3 gates x 8 states x 256 -------------
__global__ void precompute_E(const float* __restrict__ W_embed,
                             const float* __restrict__ b_embed,
                             const float* __restrict__ Wz, const float* __restrict__ bz,
                             const float* __restrict__ Wr, const float* __restrict__ br,
                             const float* __restrict__ Wh, const float* __restrict__ bh,
                             const float* __restrict__ start_embed) {
  int s = blockIdx.x;   // 0..7
  int m = blockIdx.y;   // 0..2
  int j = threadIdx.x;  // 0..255
  const float* W  = (m == 0) ? Wz : (m == 1) ? Wr : Wh;   // top 256 rows
  const float* bb = (m == 0) ? bz : (m == 1) ? br : bh;
  float acc = bb[j];
  for (int k = 0; k < HID; k++) {
    float e;
    if (s == 7) e = start_embed[k];
    else {
      e = b_embed[k];
      if (s < 6) e += W_embed[s * HID + k];
    }
    acc = fmaf(e, W[k * HID + j], acc);
  }
  g_E[m][s][j] = acc;
}

// ---------------- fused GEMM: C[64x256] tiles via packed fma.rn.f32x2 -------
// MODE 0: encoder  A=x (lda=128,K=128) -> g_h = acc + b_enc
// MODE 1: z gate   A=g_h              -> g_z  = sigmoid(acc + E_z[state])
// MODE 2: r gate   A=g_h              -> g_rh = sigmoid(acc + E_r[state]) * g_h
// MODE 3: cand     A=g_rh             -> g_h  = (1-z)*h + z*tanh(acc + E_h[state])
template <int MODE>
__global__ void __launch_bounds__(256, 2) gemm_k(
    const float* __restrict__ Aext, int lda, int K,
    const float* __restrict__ Bw, const float* __restrict__ bias) {
  constexpr int BM = 64, BN = 256, BK = 16;
  __shared__ __align__(16) float As[2][BM][BK];
  __shared__ __align__(16) float Bs[2][BK][BN];

  const float* A = (MODE == 0) ? Aext : (MODE == 3 ? g_rh : g_h);
  const int rowBase = blockIdx.x * BM;
  const int tid = threadIdx.x;
  const int tc = tid & 31;
  const int tr = tid >> 5;

  const int a_row = tid >> 2;
  const int a_seg = (tid & 3) << 2;
  const float* Ag = A + (size_t)(rowBase + a_row) * lda + a_seg;

  unsigned long long acc[8][4];
#pragma unroll
  for (int r = 0; r < 8; r++)
#pragma unroll
    for (int p = 0; p < 4; p++) acc[r][p] = 0ull;

  const int NC = K / BK;
  cp16(&As[0][a_row][a_seg], Ag);
#pragma unroll
  for (int i = 0; i < 4; i++) {
    int idx = tid + i * 256;
    int kr = idx >> 6;
    int cs = (idx & 63) << 2;
    cp16(&Bs[0][kr][cs], Bw + (size_t)kr * BN + cs);
  }
  asm volatile("cp.async.commit_group;");

  for (int c = 0; c < NC; c++) {
    if (c + 1 < NC) {
      const int kt = c + 1;
      const int buf = kt & 1;
      cp16(&As[buf][a_row][a_seg], Ag + kt * BK);
#pragma unroll
      for (int i = 0; i < 4; i++) {
        int idx = tid + i * 256;
        int kr = idx >> 6;
        int cs = (idx & 63) << 2;
        cp16(&Bs[buf][kr][cs], Bw + (size_t)(kt * BK + kr) * BN + cs);
      }
      asm volatile("cp.async.commit_group;");
      asm volatile("cp.async.wait_group 1;");
    } else {
      asm volatile("cp.async.wait_group 0;");
    }
    __syncthreads();
    const int buf = c & 1;
#pragma unroll
    for (int k = 0; k < BK; k++) {
      ulonglong2 b01 = *reinterpret_cast<const ulonglong2*>(&Bs[buf][k][tc * 4]);
      ulonglong2 b23 = *reinterpret_cast<const ulonglong2*>(&Bs[buf][k][128 + tc * 4]);
#pragma unroll
      for (int r = 0; r < 8; r++) {
        unsigned long long ap = pack2(As[buf][tr * 8 + r][k]);
        fma2(acc[r][0], ap, b01.x);
        fma2(acc[r][1], ap, b01.y);
        fma2(acc[r][2], ap, b23.x);
        fma2(acc[r][3], ap, b23.y);
      }
    }
    __syncthreads();
  }

  const int c0 = tc * 4;
#pragma unroll
  for (int r = 0; r < 8; r++) {
    const int rr = rowBase + tr * 8 + r;
    float f[8];
    {
      float2 v;
      v = unpack2(acc[r][0]); f[0] = v.x; f[1] = v.y;
      v = unpack2(acc[r][1]); f[2] = v.x; f[3] = v.y;
      v = unpack2(acc[r][2]); f[4] = v.x; f[5] = v.y;
      v = unpack2(acc[r][3]); f[6] = v.x; f[7] = v.y;
    }
    const size_t base0 = (size_t)rr * HID + c0;
    const size_t base1 = base0 + 128;
    if (MODE == 0) {
      float4 b0 = *reinterpret_cast<const float4*>(&bias[c0]);
      float4 b1 = *reinterpret_cast<const float4*>(&bias[128 + c0]);
      *reinterpret_cast<float4*>(&g_h[base0]) =
          make_float4(f[0] + b0.x, f[1] + b0.y, f[2] + b0.z, f[3] + b0.w);
      *reinterpret_cast<float4*>(&g_h[base1]) =
          make_float4(f[4] + b1.x, f[5] + b1.y, f[6] + b1.z, f[7] + b1.w);
    } else {
      const int s = g_state[rr] & 7;
      const float* Em = g_E[MODE - 1][s];
      float4 e0 = *reinterpret_cast<const float4*>(&Em[c0]);
      float4 e1 = *reinterpret_cast<const float4*>(&Em[128 + c0]);
      float pre[8] = {f[0] + e0.x, f[1] + e0.y, f[2] + e0.z, f[3] + e0.w,
                      f[4] + e1.x, f[5] + e1.y, f[6] + e1.z, f[7] + e1.w};
      if (MODE == 1) {
        *reinterpret_cast<float4*>(&g_z[base0]) =
            make_float4(sigmoid_(pre[0]), sigmoid_(pre[1]),
                        sigmoid_(pre[2]), sigmoid_(pre[3]));
        *reinterpret_cast<float4*>(&g_z[base1]) =
            make_float4(sigmoid_(pre[4]), sigmoid_(pre[5]),
                        sigmoid_(pre[6]), sigmoid_(pre[7]));
      } else if (MODE == 2) {
        float4 h0 = *reinterpret_cast<const float4*>(&g_h[base0]);
        float4 h1 = *reinterpret_cast<const float4*>(&g_h[base1]);
        *reinterpret_cast<float4*>(&g_rh[base0]) =
            make_float4(sigmoid_(pre[0]) * h0.x, sigmoid_(pre[1]) * h0.y,
                        sigmoid_(pre[2]) * h0.z, sigmoid_(pre[3]) * h0.w);
        *reinterpret_cast<float4*>(&g_rh[base1]) =
            make_float4(sigmoid_(pre[4]) * h1.x, sigmoid_(pre[5]) * h1.y,
                        sigmoid_(pre[6]) * h1.z, sigmoid_(pre[7]) * h1.w);
      } else {  // MODE 3
        float4 z0 = *reinterpret_cast<const float4*>(&g_z[base0]);
        float4 z1 = *reinterpret_cast<const float4*>(&g_z[base1]);
        float4 h0 = *reinterpret_cast<const float4*>(&g_h[base0]);
        float4 h1 = *reinterpret_cast<const float4*>(&g_h[base1]);
        float4 o0, o1;
        o0.x = (1.f - z0.x) * h0.x + z0.x * xla_tanh(pre[0]);
        o0.y = (1.f - z0.y) * h0.y + z0.y * xla_tanh(pre[1]);
        o0.z = (1.f - z0.z) * h0.z + z0.z * xla_tanh(pre[2]);
        o0.w = (1.f - z0.w) * h0.w + z0.w * xla_tanh(pre[3]);
        o1.x = (1.f - z1.x) * h1.x + z1.x * xla_tanh(pre[4]);
        o1.y = (1.f - z1.y) * h1.y + z1.y * xla_tanh(pre[5]);
        o1.z = (1.f - z1.z) * h1.z + z1.z * xla_tanh(pre[6]);
        o1.w = (1.f - z1.w) * h1.w + z1.w * xla_tanh(pre[7]);
        *reinterpret_cast<float4*>(&g_h[base0]) = o0;
        *reinterpret_cast<float4*>(&g_h[base1]) = o1;
      }
    }
  }
}

// ---------------- sampler: logits GEMV + gumbel-argmax + bookkeeping --------
__global__ void sample_step(const float* __restrict__ W_out,
                            const float* __restrict__ b_out,
                            float* __restrict__ out, int t) {
  __shared__ float Ws[HID * VTOT];
  __shared__ float bs[VTOT];
  const int tid = threadIdx.x;
  for (int i = tid; i < HID * VTOT; i += 256) Ws[i] = W_out[i];
  if (tid < VTOT) bs[tid] = b_out[tid];
  __syncthreads();

  const int b = blockIdx.x * 8 + (tid >> 5);   // one warp per row
  const int lane = tid & 31;
  const float* h = g_h + (size_t)b * HID;

  const uint32_t k0 = g_keyw[2 * t];
  const uint32_t k1 = g_keyw[2 * t + 1];

  // Partitionable random_bits: element idx -> threefry(key, (0, idx)), o0^o1.
  // Then JAX uniform(minval=tiny): u = max(tiny, f); gumbel = -log(-log(u)).
  float gf = 0.f;
  if (lane < VTOT) {
    uint32_t idx = (uint32_t)b * VTOT + lane;
    uint32_t o0, o1;
    threefry2x32(k0, k1, 0u, idx, o0, o1);
    uint32_t bits = o0 ^ o1;
    uint32_t fb = (bits >> 9) | 0x3f800000u;
    float f = __fadd_rn(__uint_as_float(fb), -1.0f);
    float u = fmaxf(1.17549435e-38f, f);
    float l1 = __nv_logf(u);            // < 0
    gf = -__nv_logf(-l1);
  }

  // logits partials: lane handles k = lane + 32*i
  float p[VTOT];
#pragma unroll
  for (int v = 0; v < VTOT; v++) p[v] = 0.f;
#pragma unroll
  for (int i = 0; i < 8; i++) {
    int k = lane + 32 * i;
    float hv = h[k];
#pragma unroll
    for (int v = 0; v < VTOT; v++) p[v] = fmaf(hv, Ws[k * VTOT + v], p[v]);
  }
#pragma unroll
  for (int o = 16; o > 0; o >>= 1) {
#pragma unroll
    for (int v = 0; v < VTOT; v++)
      p[v] += __shfl_xor_sync(0xffffffffu, p[v], o);
  }
  float gv[VTOT];
#pragma unroll
  for (int v = 0; v < VTOT; v++) gv[v] = __shfl_sync(0xffffffffu, gf, v);

  if (lane == 0) {
    unsigned char st = g_state[b];
    bool stopped = (st & 8) != 0;
    float logits[VTOT];
#pragma unroll
    for (int v = 0; v < VTOT; v++) logits[v] = p[v] + bs[v];
    int tok = 0;
    float best = logits[0] + gv[0];
#pragma unroll
    for (int v = 1; v < VTOT; v++) {
      float y = logits[v] + gv[v];
      if (y > best) { best = y; tok = v; }
    }
    float mx = logits[0];
#pragma unroll
    for (int v = 1; v < VTOT; v++) mx = fmaxf(mx, logits[v]);
    float s = 0.f;
#pragma unroll
    for (int v = 0; v < VTOT; v++)
      s = __fadd_rn(s, __nv_expf(__fadd_rn(logits[v], -mx)));
    float lp = (logits[tok] - mx) - __nv_logf(s);

    float* msg = out + (size_t)b * 36 + t * VTOT;
#pragma unroll
    for (int v = 0; v < VTOT; v++)
      msg[v] = (!stopped && v == tok) ? 1.f : 0.f;
    if (!stopped) out[(size_t)B_TOT * 36 + b] += lp;
    bool is_stop = (tok == VTOT - 1);
    if (!stopped && !is_stop) out[(size_t)B_TOT * 37 + b] += 1.f;
    bool new_stopped = stopped || is_stop;
    unsigned char ns = stopped ? 6 : (unsigned char)tok;
    g_state[b] = (unsigned char)(ns | (new_stopped ? 8 : 0));
  }
}

// ---------------- launch -----------------------------------------------------
extern "C" void kernel_launch(void* const* d_in, const int* in_sizes, int n_in,
                              void* d_out, int out_size) {
  const float* x           = (const float*)d_in[0];
  const float* W_enc       = (const float*)d_in[1];
  const float* b_enc       = (const float*)d_in[2];
  const float* W_embed     = (const float*)d_in[3];
  const float* b_embed     = (const float*)d_in[4];
  const float* W_z         = (const float*)d_in[5];
  const float* b_z         = (const float*)d_in[6];
  const float* W_r         = (const float*)d_in[7];
  const float* b_r         = (const float*)d_in[8];
  const float* W_h         = (const float*)d_in[9];
  const float* b_h         = (const float*)d_in[10];
  const float* W_out       = (const float*)d_in[11];
  const float* b_out       = (const float*)d_in[12];
  const float* start_embed = (const float*)d_in[13];
  float* out = (float*)d_out;

  init_kernel<<<B_TOT / 256, 256>>>(out);
  dim3 gE(8, 3);
  precompute_E<<<gE, 256>>>(W_embed, b_embed, W_z, b_z, W_r, b_r, W_h, b_h,
                            start_embed);

  const int GEMM_GRID = B_TOT / 64;
  gemm_k<0><<<GEMM_GRID, 256>>>(x, D_IN, D_IN, W_enc, b_enc);

  const float* Wz_bot = W_z + HID * HID;   // bottom 256 rows of (512,256)
  const float* Wr_bot = W_r + HID * HID;
  const float* Wh_bot = W_h + HID * HID;

  for (int t = 0; t < TSTEPS; t++) {
    gemm_k<1><<<GEMM_GRID, 256>>>(nullptr, HID, HID, Wz_bot, nullptr);
    gemm_k<2><<<GEMM_GRID, 256>>>(nullptr, HID, HID, Wr_bot, nullptr);
    gemm_k<3><<<GEMM_GRID, 256>>>(nullptr, HID, HID, Wh_bot, nullptr);
    sample_step<<<B_TOT / 8, 256>>>(W_out, b_out, out, t);
  }
}

// round 4
// speedup vs baseline: 1.0812x; 1.0812x over previous
#include <cuda_runtime.h>
#include <cstdint>
#include <cstddef>
#include <math.h>

#define B_TOT 131072
#define D_IN  128
#define HID   256
#define VTOT  6
#define TSTEPS 6

// libdevice direct (immune to -use_fast_math macro substitution; matches XLA)
extern "C" __device__ float __nv_logf(float);
extern "C" __device__ float __nv_expf(float);

// ---------------- persistent device scratch (no runtime allocations) -------
__device__ __align__(16) float g_h [(size_t)B_TOT * HID];
__device__ __align__(16) float g_z [(size_t)B_TOT * HID];
__device__ __align__(16) float g_rh[(size_t)B_TOT * HID];
__device__ unsigned char g_state[B_TOT];        // bits[2:0]=embed state 0..7, bit3=stopped
__device__ __align__(16) float g_E[3][8][HID];  // [z,r,h][state][j] = emb_s @ W_top + bias
__device__ uint32_t g_keyw[12];                 // partitionable split(key(42), 6)

// ---------------- threefry2x32 (exact JAX schedule) -------------------------
__device__ __forceinline__ void threefry2x32(uint32_t k0, uint32_t k1,
                                             uint32_t c0, uint32_t c1,
                                             uint32_t& o0, uint32_t& o1) {
  uint32_t ks2 = k0 ^ k1 ^ 0x1BD11BDAu;
  uint32_t x0 = c0 + k0, x1 = c1 + k1;
#define TF_R(r) { x0 += x1; x1 = (x1 << (r)) | (x1 >> (32 - (r))); x1 ^= x0; }
  TF_R(13) TF_R(15) TF_R(26) TF_R(6)
  x0 += k1;  x1 += ks2 + 1u;
  TF_R(17) TF_R(29) TF_R(16) TF_R(24)
  x0 += ks2; x1 += k0 + 2u;
  TF_R(13) TF_R(15) TF_R(26) TF_R(6)
  x0 += k0;  x1 += k1 + 3u;
  TF_R(17) TF_R(29) TF_R(16) TF_R(24)
  x0 += k1;  x1 += ks2 + 4u;
  TF_R(13) TF_R(15) TF_R(26) TF_R(6)
  x0 += ks2; x1 += k0 + 5u;
#undef TF_R
  o0 = x0; o1 = x1;
}

// ---------------- small helpers ---------------------------------------------
__device__ __forceinline__ void fma2(unsigned long long& d,
                                     unsigned long long a,
                                     unsigned long long b) {
  asm("fma.rn.f32x2 %0, %1, %2, %0;" : "+l"(d) : "l"(a), "l"(b));
}
__device__ __forceinline__ unsigned long long pack2(float a) {
  unsigned long long r;
  asm("mov.b64 %0, {%1, %1};" : "=l"(r) : "f"(a));
  return r;
}
__device__ __forceinline__ float2 unpack2(unsigned long long v) {
  float2 r;
  asm("mov.b64 {%0, %1}, %2;" : "=f"(r.x), "=f"(r.y) : "l"(v));
  return r;
}
__device__ __forceinline__ void cp16(void* dst, const void* src) {
  unsigned d = (unsigned)__cvta_generic_to_shared(dst);
  asm volatile("cp.async.cg.shared.global [%0], [%1], 16;" :: "r"(d), "l"(src));
}

// ---- XLA EmitFastTanh replication (no FMA contraction, IEEE div) -----------
__device__ __forceinline__ float xla_tanh(float x) {
  float ax = fabsf(x);
  if (ax < 0.0004f) return x;
  float xc = fminf(fmaxf(x, -9.0f), 9.0f);
  float x2 = __fmul_rn(xc, xc);
  float num = -2.76076847742355e-16f;
  num = __fadd_rn(__fmul_rn(x2, num), 2.00018790482477e-13f);
  num = __fadd_rn(__fmul_rn(x2, num), -8.60467152213735e-11f);
  num = __fadd_rn(__fmul_rn(x2, num), 5.12229709037114e-08f);
  num = __fadd_rn(__fmul_rn(x2, num), 1.48572235717979e-05f);
  num = __fadd_rn(__fmul_rn(x2, num), 6.37261928875436e-04f);
  num = __fadd_rn(__fmul_rn(x2, num), 4.89352455891786e-03f);
  num = __fmul_rn(xc, num);
  float den = 1.19825839466702e-06f;
  den = __fadd_rn(__fmul_rn(x2, den), 1.18534705686654e-04f);
  den = __fadd_rn(__fmul_rn(x2, den), 2.26843463243900e-03f);
  den = __fadd_rn(__fmul_rn(x2, den), 4.89352518554385e-03f);
  return __fdiv_rn(num, den);
}
// XLA logistic lowering: 0.5 + 0.5 * tanh(0.5 * x)
__device__ __forceinline__ float sigmoid_(float x) {
  return __fadd_rn(0.5f, __fmul_rn(0.5f, xla_tanh(__fmul_rn(0.5f, x))));
}

// ---------------- init: out accumulators, state, step keys ------------------
__global__ void init_kernel(float* __restrict__ out) {
  int i = blockIdx.x * blockDim.x + threadIdx.x;
  if (i < B_TOT) {
    out[(size_t)B_TOT * 36 + i] = 0.f;   // total_log_prob
    out[(size_t)B_TOT * 37 + i] = 0.f;   // lengths
    g_state[i] = 7;                      // start_embed, not stopped
  }
  if (i < 6) {
    uint32_t a, b;
    threefry2x32(0u, 42u, 0u, (uint32_t)i, a, b);
    g_keyw[2 * i]     = a;
    g_keyw[2 * i + 1] = b;
  }
}

// ---------------- precompute E tables: 3 gates x 8 states x 256 -------------
__global__ void precompute_E(const float* __restrict__ W_embed,
                             const float* __restrict__ b_embed,
                             const float* __restrict__ Wz, const float* __restrict__ bz,
                             const float* __restrict__ Wr, const float* __restrict__ br,
                             const float* __restrict__ Wh, const float* __restrict__ bh,
                             const float* __restrict__ start_embed) {
  int s = blockIdx.x;   // 0..7
  int m = blockIdx.y;   // 0..2
  int j = threadIdx.x;  // 0..255
  const float* W  = (m == 0) ? Wz : (m == 1) ? Wr : Wh;   // top 256 rows
  const float* bb = (m == 0) ? bz : (m == 1) ? br : bh;
  float acc = bb[j];
  for (int k = 0; k < HID; k++) {
    float e;
    if (s == 7) e = start_embed[k];
    else {
      e = b_embed[k];
      if (s < 6) e += W_embed[s * HID + k];
    }
    acc = fmaf(e, W[k * HID + j], acc);
  }
  g_E[m][s][j] = acc;
}

// ---------------- fused GEMM: C[64x256] tiles via packed fma.rn.f32x2 -------
// A tile transposed in smem (uniform LDS.128 broadcasts), single barrier/chunk.
// MODE 0: encoder  A=x (lda=128,K=128) -> g_h = acc + b_enc
// MODE 1: z gate   A=g_h              -> g_z  = sigmoid(acc + E_z[state])
// MODE 2: r gate   A=g_h              -> g_rh = sigmoid(acc + E_r[state]) * g_h
// MODE 3: cand     A=g_rh             -> g_h  = (1-z)*h + z*tanh(acc + E_h[state])
template <int MODE>
__global__ void __launch_bounds__(256, 2) gemm_k(
    const float* __restrict__ Aext, int lda, int K,
    const float* __restrict__ Bw, const float* __restrict__ bias) {
  constexpr int BM = 64, BN = 256, BK = 16, APAD = BM + 4;  // 68 floats: 16B-aligned rows
  __shared__ __align__(16) float As[2][BK][APAD];
  __shared__ __align__(16) float Bs[2][BK][BN];

  const float* A = (MODE == 0) ? Aext : (MODE == 3 ? g_rh : g_h);
  const int rowBase = blockIdx.x * BM;
  const int tid = threadIdx.x;
  const int tc = tid & 31;
  const int tr = tid >> 5;

  // A staging: thread loads A[rowBase+a_row][c*BK + a_seg .. +3] (LDG.128),
  // stores transposed As[buf][a_seg+j][a_row] (4x STS.32).
  const int a_row = tid >> 2;          // 0..63
  const int a_seg = (tid & 3) << 2;    // 0,4,8,12
  const float* Ag = A + (size_t)(rowBase + a_row) * lda + a_seg;

  unsigned long long acc[8][4];
#pragma unroll
  for (int r = 0; r < 8; r++)
#pragma unroll
    for (int p = 0; p < 4; p++) acc[r][p] = 0ull;

  const int NC = K / BK;

  // ---- prologue: stage chunk 0 (A direct, B via cp.async) ----
  float4 rA = *reinterpret_cast<const float4*>(Ag);
#pragma unroll
  for (int i = 0; i < 4; i++) {
    int idx = tid + i * 256;
    int kr = idx >> 6;
    int cs = (idx & 63) << 2;
    cp16(&Bs[0][kr][cs], Bw + (size_t)kr * BN + cs);
  }
  asm volatile("cp.async.commit_group;");
  As[0][a_seg + 0][a_row] = rA.x;
  As[0][a_seg + 1][a_row] = rA.y;
  As[0][a_seg + 2][a_row] = rA.z;
  As[0][a_seg + 3][a_row] = rA.w;
  if (NC > 1) rA = *reinterpret_cast<const float4*>(Ag + BK);

  for (int c = 0; c < NC; c++) {
    asm volatile("cp.async.wait_group 0;");
    __syncthreads();   // B(c) + As(c) visible to all; all readers of ^1 bufs done
    if (c + 1 < NC) {
      const int nbuf = (c + 1) & 1;
      // B(c+1) copy overlaps compute(c)
#pragma unroll
      for (int i = 0; i < 4; i++) {
        int idx = tid + i * 256;
        int kr = idx >> 6;
        int cs = (idx & 63) << 2;
        cp16(&Bs[nbuf][kr][cs], Bw + (size_t)((c + 1) * BK + kr) * BN + cs);
      }
      asm volatile("cp.async.commit_group;");
      As[nbuf][a_seg + 0][a_row] = rA.x;
      As[nbuf][a_seg + 1][a_row] = rA.y;
      As[nbuf][a_seg + 2][a_row] = rA.z;
      As[nbuf][a_seg + 3][a_row] = rA.w;
      if (c + 2 < NC) rA = *reinterpret_cast<const float4*>(Ag + (c + 2) * BK);
    }
    const int buf = c & 1;
#pragma unroll
    for (int k = 0; k < BK; k++) {
      ulonglong2 b01 = *reinterpret_cast<const ulonglong2*>(&Bs[buf][k][tc * 4]);
      ulonglong2 b23 = *reinterpret_cast<const ulonglong2*>(&Bs[buf][k][128 + tc * 4]);
      float4 a0 = *reinterpret_cast<const float4*>(&As[buf][k][tr * 8]);      // uniform
      float4 a1 = *reinterpret_cast<const float4*>(&As[buf][k][tr * 8 + 4]);  // uniform
      unsigned long long ap[8];
      ap[0] = pack2(a0.x); ap[1] = pack2(a0.y); ap[2] = pack2(a0.z); ap[3] = pack2(a0.w);
      ap[4] = pack2(a1.x); ap[5] = pack2(a1.y); ap[6] = pack2(a1.z); ap[7] = pack2(a1.w);
#pragma unroll
      for (int r = 0; r < 8; r++) {
        fma2(acc[r][0], ap[r], b01.x);
        fma2(acc[r][1], ap[r], b01.y);
        fma2(acc[r][2], ap[r], b23.x);
        fma2(acc[r][3], ap[r], b23.y);
      }
    }
    // no trailing barrier: next iteration's leading barrier protects buffers
  }

  // ---- epilogue: this thread owns cols [c0..c0+3] and [128+c0..128+c0+3] ---
  const int c0 = tc * 4;
#pragma unroll
  for (int r = 0; r < 8; r++) {
    const int rr = rowBase + tr * 8 + r;
    float f[8];
    {
      float2 v;
      v = unpack2(acc[r][0]); f[0] = v.x; f[1] = v.y;
      v = unpack2(acc[r][1]); f[2] = v.x; f[3] = v.y;
      v = unpack2(acc[r][2]); f[4] = v.x; f[5] = v.y;
      v = unpack2(acc[r][3]); f[6] = v.x; f[7] = v.y;
    }
    const size_t base0 = (size_t)rr * HID + c0;
    const size_t base1 = base0 + 128;
    if (MODE == 0) {
      float4 b0 = *reinterpret_cast<const float4*>(&bias[c0]);
      float4 b1 = *reinterpret_cast<const float4*>(&bias[128 + c0]);
      *reinterpret_cast<float4*>(&g_h[base0]) =
          make_float4(f[0] + b0.x, f[1] + b0.y, f[2] + b0.z, f[3] + b0.w);
      *reinterpret_cast<float4*>(&g_h[base1]) =
          make_float4(f[4] + b1.x, f[5] + b1.y, f[6] + b1.z, f[7] + b1.w);
    } else {
      const int s = g_state[rr] & 7;
      const float* Em = g_E[MODE - 1][s];
      float4 e0 = *reinterpret_cast<const float4*>(&Em[c0]);
      float4 e1 = *reinterpret_cast<const float4*>(&Em[128 + c0]);
      float pre[8] = {f[0] + e0.x, f[1] + e0.y, f[2] + e0.z, f[3] + e0.w,
                      f[4] + e1.x, f[5] + e1.y, f[6] + e1.z, f[7] + e1.w};
      if (MODE == 1) {
        *reinterpret_cast<float4*>(&g_z[base0]) =
            make_float4(sigmoid_(pre[0]), sigmoid_(pre[1]),
                        sigmoid_(pre[2]), sigmoid_(pre[3]));
        *reinterpret_cast<float4*>(&g_z[base1]) =
            make_float4(sigmoid_(pre[4]), sigmoid_(pre[5]),
                        sigmoid_(pre[6]), sigmoid_(pre[7]));
      } else if (MODE == 2) {
        float4 h0 = *reinterpret_cast<const float4*>(&g_h[base0]);
        float4 h1 = *reinterpret_cast<const float4*>(&g_h[base1]);
        *reinterpret_cast<float4*>(&g_rh[base0]) =
            make_float4(sigmoid_(pre[0]) * h0.x, sigmoid_(pre[1]) * h0.y,
                        sigmoid_(pre[2]) * h0.z, sigmoid_(pre[3]) * h0.w);
        *reinterpret_cast<float4*>(&g_rh[base1]) =
            make_float4(sigmoid_(pre[4]) * h1.x, sigmoid_(pre[5]) * h1.y,
                        sigmoid_(pre[6]) * h1.z, sigmoid_(pre[7]) * h1.w);
      } else {  // MODE 3
        float4 z0 = *reinterpret_cast<const float4*>(&g_z[base0]);
        float4 z1 = *reinterpret_cast<const float4*>(&g_z[base1]);
        float4 h0 = *reinterpret_cast<const float4*>(&g_h[base0]);
        float4 h1 = *reinterpret_cast<const float4*>(&g_h[base1]);
        float4 o0, o1;
        o0.x = (1.f - z0.x) * h0.x + z0.x * xla_tanh(pre[0]);
        o0.y = (1.f - z0.y) * h0.y + z0.y * xla_tanh(pre[1]);
        o0.z = (1.f - z0.z) * h0.z + z0.z * xla_tanh(pre[2]);
        o0.w = (1.f - z0.w) * h0.w + z0.w * xla_tanh(pre[3]);
        o1.x = (1.f - z1.x) * h1.x + z1.x * xla_tanh(pre[4]);
        o1.y = (1.f - z1.y) * h1.y + z1.y * xla_tanh(pre[5]);
        o1.z = (1.f - z1.z) * h1.z + z1.z * xla_tanh(pre[6]);
        o1.w = (1.f - z1.w) * h1.w + z1.w * xla_tanh(pre[7]);
        *reinterpret_cast<float4*>(&g_h[base0]) = o0;
        *reinterpret_cast<float4*>(&g_h[base1]) = o1;
      }
    }
  }
}

// ---------------- sampler: logits GEMV + gumbel-argmax + bookkeeping --------
__global__ void sample_step(const float* __restrict__ W_out,
                            const float* __restrict__ b_out,
                            float* __restrict__ out, int t) {
  __shared__ float Ws[HID * VTOT];
  __shared__ float bs[VTOT];
  const int tid = threadIdx.x;
  for (int i = tid; i < HID * VTOT; i += 256) Ws[i] = W_out[i];
  if (tid < VTOT) bs[tid] = b_out[tid];
  __syncthreads();

  const int b = blockIdx.x * 8 + (tid >> 5);   // one warp per row
  const int lane = tid & 31;
  const float* h = g_h + (size_t)b * HID;

  const uint32_t k0 = g_keyw[2 * t];
  const uint32_t k1 = g_keyw[2 * t + 1];

  // Partitionable random_bits: element idx -> threefry(key, (0, idx)), o0^o1.
  float gf = 0.f;
  if (lane < VTOT) {
    uint32_t idx = (uint32_t)b * VTOT + lane;
    uint32_t o0, o1;
    threefry2x32(k0, k1, 0u, idx, o0, o1);
    uint32_t bits = o0 ^ o1;
    uint32_t fb = (bits >> 9) | 0x3f800000u;
    float f = __fadd_rn(__uint_as_float(fb), -1.0f);
    float u = fmaxf(1.17549435e-38f, f);
    float l1 = __nv_logf(u);            // < 0
    gf = -__nv_logf(-l1);
  }

  float p[VTOT];
#pragma unroll
  for (int v = 0; v < VTOT; v++) p[v] = 0.f;
#pragma unroll
  for (int i = 0; i < 8; i++) {
    int k = lane + 32 * i;
    float hv = h[k];
#pragma unroll
    for (int v = 0; v < VTOT; v++) p[v] = fmaf(hv, Ws[k * VTOT + v], p[v]);
  }
#pragma unroll
  for (int o = 16; o > 0; o >>= 1) {
#pragma unroll
    for (int v = 0; v < VTOT; v++)
      p[v] += __shfl_xor_sync(0xffffffffu, p[v], o);
  }
  float gv[VTOT];
#pragma unroll
  for (int v = 0; v < VTOT; v++) gv[v] = __shfl_sync(0xffffffffu, gf, v);

  if (lane == 0) {
    unsigned char st = g_state[b];
    bool stopped = (st & 8) != 0;
    float logits[VTOT];
#pragma unroll
    for (int v = 0; v < VTOT; v++) logits[v] = p[v] + bs[v];
    int tok = 0;
    float best = logits[0] + gv[0];
#pragma unroll
    for (int v = 1; v < VTOT; v++) {
      float y = logits[v] + gv[v];
      if (y > best) { best = y; tok = v; }
    }
    float mx = logits[0];
#pragma unroll
    for (int v = 1; v < VTOT; v++) mx = fmaxf(mx, logits[v]);
    float s = 0.f;
#pragma unroll
    for (int v = 0; v < VTOT; v++)
      s = __fadd_rn(s, __nv_expf(__fadd_rn(logits[v], -mx)));
    float lp = (logits[tok] - mx) - __nv_logf(s);

    float* msg = out + (size_t)b * 36 + t * VTOT;
#pragma unroll
    for (int v = 0; v < VTOT; v++)
      msg[v] = (!stopped && v == tok) ? 1.f : 0.f;
    if (!stopped) out[(size_t)B_TOT * 36 + b] += lp;
    bool is_stop = (tok == VTOT - 1);
    if (!stopped && !is_stop) out[(size_t)B_TOT * 37 + b] += 1.f;
    bool new_stopped = stopped || is_stop;
    unsigned char ns = stopped ? 6 : (unsigned char)tok;
    g_state[b] = (unsigned char)(ns | (new_stopped ? 8 : 0));
  }
}

// ---------------- launch -----------------------------------------------------
extern "C" void kernel_launch(void* const* d_in, const int* in_sizes, int n_in,
                              void* d_out, int out_size) {
  const float* x           = (const float*)d_in[0];
  const float* W_enc       = (const float*)d_in[1];
  const float* b_enc       = (const float*)d_in[2];
  const float* W_embed     = (const float*)d_in[3];
  const float* b_embed     = (const float*)d_in[4];
  const float* W_z         = (const float*)d_in[5];
  const float* b_z         = (const float*)d_in[6];
  const float* W_r         = (const float*)d_in[7];
  const float* b_r         = (const float*)d_in[8];
  const float* W_h         = (const float*)d_in[9];
  const float* b_h         = (const float*)d_in[10];
  const float* W_out       = (const float*)d_in[11];
  const float* b_out       = (const float*)d_in[12];
  const float* start_embed = (const float*)d_in[13];
  float* out = (float*)d_out;

  init_kernel<<<B_TOT / 256, 256>>>(out);
  dim3 gE(8, 3);
  precompute_E<<<gE, 256>>>(W_embed, b_embed, W_z, b_z, W_r, b_r, W_h, b_h,
                            start_embed);

  const int GEMM_GRID = B_TOT / 64;
  gemm_k<0><<<GEMM_GRID, 256>>>(x, D_IN, D_IN, W_enc, b_enc);

  const float* Wz_bot = W_z + HID * HID;   // bottom 256 rows of (512,256)
  const float* Wr_bot = W_r + HID * HID;
  const float* Wh_bot = W_h + HID * HID;

  for (int t = 0; t < TSTEPS; t++) {
    gemm_k<1><<<GEMM_GRID, 256>>>(nullptr, HID, HID, Wz_bot, nullptr);
    gemm_k<2><<<GEMM_GRID, 256>>>(nullptr, HID, HID, Wr_bot, nullptr);
    gemm_k<3><<<GEMM_GRID, 256>>>(nullptr, HID, HID, Wh_bot, nullptr);
    sample_step<<<B_TOT / 8, 256>>>(W_out, b_out, out, t);
  }
}